// round 14
// baseline (speedup 1.0000x reference)
#include <cuda_runtime.h>
#include <cuda_bf16.h>
#include <cstdint>

// ===========================================================================
// Goal_Conditioned_Policies forward, persistent-CTA conv + warp-per-sample MLP.
// K1: one CTA per SM (1024 thr), grid-strides over samples.
//     conv1: DENSE K=48 (XE pair-cells + XO odd-cells, mixed-address ldsm),
//            32 warps x 2m x 4n.
//     conv2: warp-specialized — warps 0-15 GEMM (2m x 4n), 16-31 stage next x.
// K2: warp-per-sample MLP + C matvec + softmax in registers via shfl.
// ===========================================================================

#define NTHREADS  1024
#define NVAR      50
#define B_SAMPLES 4096

// ---- K1 smem byte offsets ----
#define XE_OFF   0u            // [2 py][33 iy][32 j][16B] = 33,792
#define XE_PY    16896u
#define XO_OFF   33792u        // [2 py][33 iy][33 j][16B] = 34,848
#define XO_PY    17424u
#define P_OFF    68640u        // [4 pyx][4 g][17][17][16B] = 73,984
#define P_REG    4624u
#define B1_OFF   142624u       // conv1 weights [48 k][80 B rows] = 3,840
#define B2_OFF   146464u       // conv2 weights [288 k][144 B rows] = 41,472
#define VEC_OFF  187936u
#define SMEM_BYTES 190464u

// vec float indices
#define V_B1S  0
#define V_B2S  32
#define V_PP   96        // pool partials [16 conv2-warps][32]

__device__ __forceinline__ uint32_t smem_u32(const void* p) {
    uint32_t a;
    asm("{ .reg .u64 t; cvta.to.shared.u64 t, %1; cvt.u32.u64 %0, t; }" : "=r"(a) : "l"(p));
    return a;
}
__device__ __forceinline__ void ldsm_x4(uint32_t* r, uint32_t addr) {
    asm volatile("ldmatrix.sync.aligned.m8n8.x4.shared.b16 {%0,%1,%2,%3}, [%4];"
        : "=r"(r[0]), "=r"(r[1]), "=r"(r[2]), "=r"(r[3]) : "r"(addr));
}
__device__ __forceinline__ void ldsm_x4_t(uint32_t* r, uint32_t addr) {
    asm volatile("ldmatrix.sync.aligned.m8n8.x4.trans.shared.b16 {%0,%1,%2,%3}, [%4];"
        : "=r"(r[0]), "=r"(r[1]), "=r"(r[2]), "=r"(r[3]) : "r"(addr));
}
__device__ __forceinline__ void mma16816(float* d, const uint32_t* a, const uint32_t* b) {
    asm volatile(
        "mma.sync.aligned.m16n8k16.row.col.f32.bf16.bf16.f32 "
        "{%0,%1,%2,%3}, {%4,%5,%6,%7}, {%8,%9}, {%0,%1,%2,%3};"
        : "+f"(d[0]), "+f"(d[1]), "+f"(d[2]), "+f"(d[3])
        : "r"(a[0]), "r"(a[1]), "r"(a[2]), "r"(a[3]), "r"(b[0]), "r"(b[1]));
}
__device__ __forceinline__ uint32_t pack_bf16x2(float lo, float hi) {
    uint32_t r;
    asm("cvt.rn.bf16x2.f32 %0, %1, %2;" : "=r"(r) : "f"(hi), "f"(lo));
    return r;
}

// --- global scratch (static device arrays; rebuilt deterministically) ---
__device__ __align__(16) __nv_bfloat16 g_B1[48 * 40];
__device__ __align__(16) __nv_bfloat16 g_B2[288 * 72];
__device__ __align__(16) float g_pool[B_SAMPLES * 64];

// conv1 dense K map: k = ks*16 + sl (ks = ky):
//   sl 0-2  -> tap (ky, kx=1), ic = sl       (XE even-pixel slots)
//   sl 4-6  -> tap (ky, kx=2), ic = sl-4     (XE odd-pixel slots)
//   sl 8-10 -> tap (ky, kx=0), ic = sl-8     (XO slots)
//   else 0
__global__ void w_prep_kernel(const float* __restrict__ w1, const float* __restrict__ w2) {
    int i = blockIdx.x * blockDim.x + threadIdx.x;
    if (i < 48 * 40) {
        int kk = i / 40, slot = i - kk * 40;
        int ks = kk >> 4, sl = kk & 15;
        float v = 0.f;
        if (slot < 32) {
            int ic = -1, tap = 0;
            if (sl < 3)                  { ic = sl;     tap = ks * 3 + 1; }
            else if (sl >= 4 && sl < 7)  { ic = sl - 4; tap = ks * 3 + 2; }
            else if (sl >= 8 && sl < 11) { ic = sl - 8; tap = ks * 3 + 0; }
            if (ic >= 0) v = w1[slot * 27 + ic * 9 + tap];   // w1[oc][ic][tap]
        }
        g_B1[i] = __float2bfloat16(v);
    }
    int i2 = i - 48 * 40;
    if (i2 >= 0 && i2 < 288 * 72) {
        int kk = i2 / 72, slot = i2 - kk * 72;
        int tap = kk >> 5, ic = kk & 31;
        float v = (slot < 64) ? w2[(slot * 32 + ic) * 9 + tap] : 0.f;
        g_B2[i2] = __float2bfloat16(v);
    }
}

// Stage sample's x: pixel (Y,X) -> py=Y&1, iy=(Y+1)>>1.
//   X even (=2j): XE[py][iy][j] slots 0-3
//   X odd (=2j+1): XE[py][iy][j] slots 4-7  AND  XO[py][iy][j+1] slots 0-3
// Pad slots / halo cells zeroed once at setup, never overwritten.
template<int NT>
__device__ __forceinline__ void stage_x(char* smc, int t, const float* __restrict__ x, int s) {
    const float* xb = x + (size_t)s * 12288;
    #pragma unroll
    for (int it = 0; it < 4096 / NT; it++) {
        int i = it * NT + t;                    // pixel index 0..4095
        float v0 = xb[i];
        float v1 = xb[4096 + i];
        float v2 = xb[8192 + i];
        uint2 q;
        q.x = pack_bf16x2(v0, v1);
        q.y = pack_bf16x2(v2, 0.f);
        int Y = i >> 6, X = i & 63;
        int py = Y & 1, iy = (Y + 1) >> 1;
        int j = X >> 1;
        if ((X & 1) == 0) {
            *(uint2*)(smc + XE_OFF + (uint32_t)py * XE_PY + (uint32_t)(iy * 32 + j) * 16u) = q;
        } else {
            *(uint2*)(smc + XE_OFF + (uint32_t)py * XE_PY + (uint32_t)(iy * 32 + j) * 16u + 8u) = q;
            *(uint2*)(smc + XO_OFF + (uint32_t)py * XO_PY + (uint32_t)(iy * 33 + j + 1) * 16u) = q;
        }
    }
}

// ===========================================================================
// K1: persistent convs + pool (1024 threads, 32 warps, 1 CTA/SM)
// ===========================================================================
__global__ __launch_bounds__(NTHREADS, 1)
void gcp_conv_kernel(const float* __restrict__ x,
                     const float* __restrict__ b1, const float* __restrict__ b2)
{
    extern __shared__ char smc[];
    const uint32_t smaddr = smem_u32(smc);
    const int tid  = threadIdx.x;
    const int wrp  = tid >> 5;
    const int lane = tid & 31;
    float* vec = (float*)(smc + VEC_OFF);

    // ---- one-time setup: zero XE+XO (pads+halos), P halos, B1/B2, biases ----
    {
        uint4 z = make_uint4(0, 0, 0, 0);
        for (int i = tid; i < 4290; i += NTHREADS)      // XE+XO = 68,640 B
            ((uint4*)(smc + XE_OFF))[i] = z;
        for (int i = tid; i < 544; i += NTHREADS) {
            int c = i / 34, r = i - c * 34;
            int pyx = c >> 2, g = c & 3;
            int py = pyx >> 1, px = pyx & 1;
            int iy_h = (py == 0) ? 0 : 16;
            int ix_h = (px == 0) ? 0 : 16;
            int iy, ix;
            if (r < 17) { iy = iy_h; ix = r; }
            else        { iy = r - 17; ix = ix_h; }
            *(uint4*)(smc + P_OFF + (uint32_t)(pyx * 4 + g) * P_REG
                      + (uint32_t)(iy * 17 + ix) * 16u) = z;
        }
        const uint4* gb1 = (const uint4*)g_B1;
        for (int i = tid; i < 240; i += NTHREADS)
            ((uint4*)(smc + B1_OFF))[i] = gb1[i];
        const uint4* gb2 = (const uint4*)g_B2;
        for (int i = tid; i < 2592; i += NTHREADS)
            ((uint4*)(smc + B2_OFF))[i] = gb2[i];
        if (tid < 32) vec[V_B1S + tid] = b1[tid];
        else if (tid < 96) vec[V_B2S + tid - 32] = b2[tid - 32];
    }
    __syncthreads();   // zero-init must complete before interior staging
    if ((int)blockIdx.x < B_SAMPLES) stage_x<NTHREADS>(smc, tid, x, blockIdx.x);
    __syncthreads();

    const int r8    = lane & 7;
    const int msel  = (lane >> 3) & 1;
    const int khsel = lane >> 4;
    const int stride = gridDim.x;
    const int ox2   = msel * 8 + r8;

    for (int s = blockIdx.x; s < B_SAMPLES; s += stride) {
        // =================================================================
        // conv1 GEMM: D1[1024][32], DENSE K=48 (3 ks). Warps: m-tiles {2w,2w+1}.
        // A ldsm: lanes 0-15 -> XE pair-cells (k0-7), lanes 16-31 -> XO (k8-15).
        // =================================================================
        float acc1[2][4][4];
        #pragma unroll
        for (int mt = 0; mt < 2; mt++)
            #pragma unroll
            for (int nt = 0; nt < 4; nt++)
                #pragma unroll
                for (int rg = 0; rg < 4; rg++) acc1[mt][nt][rg] = 0.f;
        {
            #pragma unroll
            for (int ks = 0; ks < 3; ks++) {
                uint32_t bf[2][4];
                uint32_t bb = smaddr + B1_OFF + (uint32_t)(ks * 16 + (lane & 15)) * 80u
                              + (uint32_t)(lane >> 4) * 16u;
                ldsm_x4_t(bf[0], bb);
                ldsm_x4_t(bf[1], bb + 32u);

                const int ky  = ks;
                const int pyA = (ky + 1) & 1;
                uint32_t af[2][4];
                #pragma unroll
                for (int mt = 0; mt < 2; mt++) {
                    int pos = (wrp * 2 + mt) * 16 + msel * 8 + r8;
                    int oy = pos >> 5, ox = pos & 31;
                    int iyA = oy + (ky >> 1);
                    uint32_t addrE = XE_OFF + (uint32_t)pyA * XE_PY
                                   + (uint32_t)(iyA * 32 + ox) * 16u;
                    uint32_t addrO = XO_OFF + (uint32_t)pyA * XO_PY
                                   + (uint32_t)(iyA * 33 + ox) * 16u;
                    ldsm_x4(af[mt], smaddr + (khsel ? addrO : addrE));
                }
                #pragma unroll
                for (int mt = 0; mt < 2; mt++)
                    #pragma unroll
                    for (int nt = 0; nt < 4; nt++)
                        mma16816(acc1[mt][nt], af[mt], &bf[nt >> 1][(nt & 1) * 2]);
            }
        }
        // ---- writeback: relu(acc1 + b1) -> P ----
        {
            #pragma unroll
            for (int nt = 0; nt < 4; nt++) {
                int n = nt * 8 + (lane & 3) * 2;
                float bb0 = vec[V_B1S + n], bb1 = vec[V_B1S + n + 1];
                uint32_t greg = (uint32_t)(n >> 3) * P_REG;
                uint32_t sub  = (uint32_t)(n & 7) * 2u;
                #pragma unroll
                for (int mt = 0; mt < 2; mt++) {
                    #pragma unroll
                    for (int hh = 0; hh < 2; hh++) {
                        int pos = (wrp * 2 + mt) * 16 + (lane >> 2) + hh * 8;
                        int Y = (pos >> 5) + 1, X = (pos & 31) + 1;
                        float v0 = fmaxf(acc1[mt][nt][hh * 2 + 0] + bb0, 0.f);
                        float v1 = fmaxf(acc1[mt][nt][hh * 2 + 1] + bb1, 0.f);
                        uint32_t off = P_OFF + (uint32_t)((Y & 1) * 2 + (X & 1)) * (4u * P_REG)
                            + greg + (uint32_t)((Y >> 1) * 17 + (X >> 1)) * 16u + sub;
                        *(uint32_t*)(smc + off) = pack_bf16x2(v0, v1);
                    }
                }
            }
        }
        __syncthreads();   // A: P ready; conv1's XE/XO reads done

        int sn = s + stride;
        if (wrp >= 16) {
            // ---- copy warps: stage next sample during conv2 ----
            if (sn < B_SAMPLES) stage_x<512>(smc, tid - 512, x, sn);
        } else {
            // =============================================================
            // conv2 GEMM: D2[256][64]. 16 warps, fat tiles:
            // warp w: m-tiles {2(w&7), 2(w&7)+1}, n-half (w>>3).
            // =============================================================
            const int mt0 = (wrp & 7) * 2;
            const int nh  = wrp >> 3;
            float acc2[2][4][4];
            #pragma unroll
            for (int jl = 0; jl < 4; jl++) {
                int oc = nh * 32 + jl * 8 + (lane & 3) * 2;
                float b0  = vec[V_B2S + oc];
                float b1v = vec[V_B2S + oc + 1];
                #pragma unroll
                for (int mt = 0; mt < 2; mt++) {
                    acc2[mt][jl][0] = b0;  acc2[mt][jl][1] = b1v;
                    acc2[mt][jl][2] = b0;  acc2[mt][jl][3] = b1v;
                }
            }
            #pragma unroll
            for (int tap = 0; tap < 9; tap++) {
                const int ky = tap / 3, kx = tap - 3 * ky;
                const uint32_t pbase = P_OFF
                    + (uint32_t)((ky & 1) * 2 + (kx & 1)) * (4u * P_REG)
                    + (uint32_t)khsel * P_REG + (uint32_t)(ox2 + (kx >> 1)) * 16u;
                #pragma unroll
                for (int gh = 0; gh < 2; gh++) {
                    uint32_t af[2][4];
                    #pragma unroll
                    for (int mt = 0; mt < 2; mt++) {
                        uint32_t ra = pbase + (uint32_t)gh * (2u * P_REG)
                            + (uint32_t)((mt0 + mt + (ky >> 1)) * 17) * 16u;
                        ldsm_x4(af[mt], smaddr + ra);
                    }
                    uint32_t bf[2][4];
                    uint32_t bb = smaddr + B2_OFF
                        + (uint32_t)((tap * 32 + gh * 16) + (lane & 15)) * 144u
                        + (uint32_t)(lane >> 4) * 16u + (uint32_t)(2 * nh) * 32u;
                    ldsm_x4_t(bf[0], bb);
                    ldsm_x4_t(bf[1], bb + 32u);
                    #pragma unroll
                    for (int mt = 0; mt < 2; mt++)
                        #pragma unroll
                        for (int jl = 0; jl < 4; jl++)
                            mma16816(acc2[mt][jl], af[mt], &bf[jl >> 1][(jl & 1) * 2]);
                }
            }
            // ---- relu + meanpool partials ----
            #pragma unroll
            for (int jl = 0; jl < 4; jl++) {
                float s0 = 0.f, s1 = 0.f;
                #pragma unroll
                for (int mt = 0; mt < 2; mt++) {
                    s0 += fmaxf(acc2[mt][jl][0], 0.f) + fmaxf(acc2[mt][jl][2], 0.f);
                    s1 += fmaxf(acc2[mt][jl][1], 0.f) + fmaxf(acc2[mt][jl][3], 0.f);
                }
                s0 += __shfl_xor_sync(0xffffffffu, s0, 4);
                s1 += __shfl_xor_sync(0xffffffffu, s1, 4);
                s0 += __shfl_xor_sync(0xffffffffu, s0, 8);
                s1 += __shfl_xor_sync(0xffffffffu, s1, 8);
                s0 += __shfl_xor_sync(0xffffffffu, s0, 16);
                s1 += __shfl_xor_sync(0xffffffffu, s1, 16);
                if (lane < 4) {
                    vec[V_PP + wrp * 32 + jl * 8 + lane * 2]     = s0;
                    vec[V_PP + wrp * 32 + jl * 8 + lane * 2 + 1] = s1;
                }
            }
        }
        __syncthreads();   // B: PP ready; next sample staged

        if (tid < 64) {
            int nhh = tid >> 5, oc32 = tid & 31;
            float sacc = 0.f;
            #pragma unroll
            for (int mp = 0; mp < 8; mp++)
                sacc += vec[V_PP + (nhh * 8 + mp) * 32 + oc32];
            g_pool[s * 64 + nhh * 32 + oc32] = sacc * (1.f / 256.f);
        }
        // PP reads finish before any warp passes next iteration's sync A,
        // which precedes the next conv2's PP writes — no extra barrier needed.
    }
}

// ===========================================================================
// K2: warp-per-sample MLP + C matvec + softmax. No smem, no barriers.
// ===========================================================================
__global__ __launch_bounds__(256, 4)
void gcp_mlp_kernel(const float* __restrict__ C,
                    const float* __restrict__ encw, const float* __restrict__ encb,
                    const float* __restrict__ f1w,  const float* __restrict__ f1b,
                    const float* __restrict__ f2w,  const float* __restrict__ f2b,
                    const float* __restrict__ f3w,  const float* __restrict__ f3b,
                    const float* __restrict__ f4w,  const float* __restrict__ f4b,
                    const float* __restrict__ f5w,  const float* __restrict__ f5b,
                    const float* __restrict__ ow,   const float* __restrict__ ob,
                    float* __restrict__ out)
{
    const int s    = blockIdx.x * 8 + (threadIdx.x >> 5);
    const int lane = threadIdx.x & 31;
    const unsigned FULL = 0xffffffffu;

    const float p0 = g_pool[s * 64 + lane];
    const float p1 = g_pool[s * 64 + 32 + lane];

    float x1r[4];
    #pragma unroll
    for (int j = 0; j < 4; j++) x1r[j] = encb[lane + 32 * j];
    #pragma unroll 4
    for (int k = 0; k < 64; k++) {
        float v = (k < 32) ? __shfl_sync(FULL, p0, k) : __shfl_sync(FULL, p1, k - 32);
        #pragma unroll
        for (int j = 0; j < 4; j++)
            x1r[j] = fmaf(v, __ldg(&encw[k * 128 + lane + 32 * j]), x1r[j]);
    }
    #pragma unroll
    for (int j = 0; j < 4; j++) x1r[j] = fmaxf(x1r[j], 0.f);

    float a0 = f1b[lane];
    float a1 = (lane < 18) ? f1b[lane + 32] : 0.f;
    const int nc = (lane < 18) ? lane + 32 : 49;
    #pragma unroll 4
    for (int k = 0; k < 128; k++) {
        float v = __shfl_sync(FULL, x1r[k >> 5], k & 31);
        a0 = fmaf(v, __ldg(&f1w[k * NVAR + lane]), a0);
        a1 = fmaf(v, __ldg(&f1w[k * NVAR + nc]), a1);
    }
    float x2a = fmaxf(a0, 0.f);
    float x2b = fmaxf(a1, 0.f);

    float ea = 0.f, eb = 0.f;
    {
        const float* cs = C + (size_t)s * 2500;
        for (int n = 0; n < NVAR; n++) {
            float t = __ldg(&cs[n * NVAR + lane]) * x2a;
            if (lane < 18) t = fmaf(__ldg(&cs[n * NVAR + 32 + lane]), x2b, t);
            #pragma unroll
            for (int off = 16; off > 0; off >>= 1)
                t += __shfl_xor_sync(FULL, t, off);
            if (n < 32) { if (lane == n) ea = t; }
            else        { if (lane == n - 32) eb = t; }
        }
    }

    float x3r[4];
    #pragma unroll
    for (int j = 0; j < 4; j++) x3r[j] = f2b[lane + 32 * j];
    #pragma unroll 2
    for (int k = 0; k < NVAR; k++) {
        float v = (k < 32) ? __shfl_sync(FULL, ea, k) : __shfl_sync(FULL, eb, k - 32);
        #pragma unroll
        for (int j = 0; j < 4; j++)
            x3r[j] = fmaf(v, __ldg(&f2w[k * 128 + lane + 32 * j]), x3r[j]);
    }
    #pragma unroll
    for (int j = 0; j < 4; j++) x3r[j] = fmaxf(x3r[j], 0.f);

    float b0 = f3b[lane], b1v = f3b[lane + 32];
    #pragma unroll 4
    for (int k = 0; k < 256; k++) {
        float v = (k < 128) ? __shfl_sync(FULL, x1r[k >> 5], k & 31)
                            : __shfl_sync(FULL, x3r[(k - 128) >> 5], (k - 128) & 31);
        b0  = fmaf(v, __ldg(&f3w[k * 64 + lane]), b0);
        b1v = fmaf(v, __ldg(&f3w[k * 64 + lane + 32]), b1v);
    }
    float x5a = fmaxf(b0, 0.f), x5b = fmaxf(b1v, 0.f);

    float c0 = f4b[lane], c1 = f4b[lane + 32];
    #pragma unroll 4
    for (int k = 0; k < 64; k++) {
        float v = (k < 32) ? __shfl_sync(FULL, x5a, k) : __shfl_sync(FULL, x5b, k - 32);
        c0 = fmaf(v, __ldg(&f4w[k * 64 + lane]), c0);
        c1 = fmaf(v, __ldg(&f4w[k * 64 + lane + 32]), c1);
    }
    float x6a = fmaxf(c0, 0.f), x6b = fmaxf(c1, 0.f);

    float d0 = f5b[lane], d1 = f5b[lane + 32];
    #pragma unroll 4
    for (int k = 0; k < 64; k++) {
        float v = (k < 32) ? __shfl_sync(FULL, x6a, k) : __shfl_sync(FULL, x6b, k - 32);
        d0 = fmaf(v, __ldg(&f5w[k * 64 + lane]), d0);
        d1 = fmaf(v, __ldg(&f5w[k * 64 + lane + 32]), d1);
    }
    float x7a = fmaxf(d0, 0.f), x7b = fmaxf(d1, 0.f);

    float l0 = ob[lane];
    float l1 = (lane < 18) ? ob[lane + 32] : 0.f;
    #pragma unroll 4
    for (int k = 0; k < 64; k++) {
        float v = (k < 32) ? __shfl_sync(FULL, x7a, k) : __shfl_sync(FULL, x7b, k - 32);
        l0 = fmaf(v, __ldg(&ow[k * NVAR + lane]), l0);
        l1 = fmaf(v, __ldg(&ow[k * NVAR + nc]), l1);
    }
    l0 = fmaxf(l0, 0.f);
    l1 = (lane < 18) ? fmaxf(l1, 0.f) : -1e30f;

    float m = fmaxf(l0, l1);
    #pragma unroll
    for (int off = 16; off > 0; off >>= 1)
        m = fmaxf(m, __shfl_xor_sync(FULL, m, off));
    float e0 = expf(l0 - m);
    float e1 = (lane < 18) ? expf(l1 - m) : 0.f;
    float ssum = e0 + e1;
    #pragma unroll
    for (int off = 16; off > 0; off >>= 1)
        ssum += __shfl_xor_sync(FULL, ssum, off);
    float inv = 1.f / ssum;
    out[s * NVAR + lane] = e0 * inv;
    if (lane < 18) out[s * NVAR + 32 + lane] = e1 * inv;
}

extern "C" void kernel_launch(void* const* d_in, const int* in_sizes, int n_in,
                              void* d_out, int out_size)
{
    (void)in_sizes; (void)n_in; (void)out_size;
    const float* x    = (const float*)d_in[0];
    const float* C    = (const float*)d_in[1];
    const float* w1   = (const float*)d_in[2];
    const float* b1   = (const float*)d_in[3];
    const float* w2   = (const float*)d_in[4];
    const float* b2   = (const float*)d_in[5];
    const float* encw = (const float*)d_in[6];
    const float* encb = (const float*)d_in[7];
    const float* f1w  = (const float*)d_in[8];
    const float* f1b  = (const float*)d_in[9];
    const float* f2w  = (const float*)d_in[10];
    const float* f2b  = (const float*)d_in[11];
    const float* f3w  = (const float*)d_in[12];
    const float* f3b  = (const float*)d_in[13];
    const float* f4w  = (const float*)d_in[14];
    const float* f4b  = (const float*)d_in[15];
    const float* f5w  = (const float*)d_in[16];
    const float* f5b  = (const float*)d_in[17];
    const float* ow   = (const float*)d_in[18];
    const float* ob   = (const float*)d_in[19];
    float* out = (float*)d_out;

    int nsm = 148;
    cudaDeviceGetAttribute(&nsm, cudaDevAttrMultiProcessorCount, 0);

    w_prep_kernel<<<89, 256>>>(w1, w2);

    cudaFuncSetAttribute(gcp_conv_kernel,
                         cudaFuncAttributeMaxDynamicSharedMemorySize, SMEM_BYTES);
    gcp_conv_kernel<<<nsm, NTHREADS, SMEM_BYTES>>>(x, b1, b2);

    gcp_mlp_kernel<<<B_SAMPLES / 8, 256>>>(C, encw, encb, f1w, f1b, f2w, f2b,
                                           f3w, f3b, f4w, f4b, f5w, f5b, ow, ob, out);
}

// round 15
// speedup vs baseline: 1.2885x; 1.2885x over previous
#include <cuda_runtime.h>
#include <cuda_bf16.h>
#include <cstdint>

// ===========================================================================
// Goal_Conditioned_Policies forward, persistent-CTA conv + warp-per-sample MLP.
// K1: one CTA per SM (1024 thr), grid-strides over samples.
//     conv1: 32 warps (2 m-tiles each). conv2: WARP-SPECIALIZED —
//     warps 0-15 run GEMM with fat 2m x 4n tiles, warps 16-31 stage next x.
//     Weight matrices built in smem directly from w1/w2 at setup (no prep
//     kernel). Three pad launches precede K1 so ncu (-s 5 -c 1) captures it.
// K2: warp-per-sample MLP + C matvec + softmax in registers via shfl.
// ===========================================================================

#define NTHREADS  1024
#define NVAR      50
#define B_SAMPLES 4096

// ---- K1 smem byte offsets ----
#define XQ_OFF   0u            // [4 pyx][33][33][16B] = 69,696
#define P_OFF    69696u        // [4 pyx][4 g][17][17][16B] = 73,984
#define B1_OFF   143680u       // conv1 weights [80 k][80 B rows] = 6,400
#define B2_OFF   150080u       // conv2 weights [288 k][144 B rows] = 41,472
#define VEC_OFF  191552u
#define SMEM_BYTES 196096u

#define XQ_REG 17424u          // 33*33*16
#define P_REG  4624u           // 17*17*16

// vec float indices
#define V_B1S  0
#define V_B2S  32
#define V_PP   96        // pool partials [16 conv2-warps][32]

__device__ __forceinline__ uint32_t smem_u32(const void* p) {
    uint32_t a;
    asm("{ .reg .u64 t; cvta.to.shared.u64 t, %1; cvt.u32.u64 %0, t; }" : "=r"(a) : "l"(p));
    return a;
}
__device__ __forceinline__ void ldsm_x4(uint32_t* r, uint32_t addr) {
    asm volatile("ldmatrix.sync.aligned.m8n8.x4.shared.b16 {%0,%1,%2,%3}, [%4];"
        : "=r"(r[0]), "=r"(r[1]), "=r"(r[2]), "=r"(r[3]) : "r"(addr));
}
__device__ __forceinline__ void ldsm_x4_t(uint32_t* r, uint32_t addr) {
    asm volatile("ldmatrix.sync.aligned.m8n8.x4.trans.shared.b16 {%0,%1,%2,%3}, [%4];"
        : "=r"(r[0]), "=r"(r[1]), "=r"(r[2]), "=r"(r[3]) : "r"(addr));
}
__device__ __forceinline__ void mma16816(float* d, const uint32_t* a, const uint32_t* b) {
    asm volatile(
        "mma.sync.aligned.m16n8k16.row.col.f32.bf16.bf16.f32 "
        "{%0,%1,%2,%3}, {%4,%5,%6,%7}, {%8,%9}, {%0,%1,%2,%3};"
        : "+f"(d[0]), "+f"(d[1]), "+f"(d[2]), "+f"(d[3])
        : "r"(a[0]), "r"(a[1]), "r"(a[2]), "r"(a[3]), "r"(b[0]), "r"(b[1]));
}
__device__ __forceinline__ uint32_t pack_bf16x2(float lo, float hi) {
    uint32_t r;
    asm("cvt.rn.bf16x2.f32 %0, %1, %2;" : "=r"(r) : "f"(hi), "f"(lo));
    return r;
}

// --- global scratch ---
__device__ __align__(16) float g_pool[B_SAMPLES * 64];

// ncu alignment pads (empty; shift capture onto gcp_conv_kernel)
__global__ void pad_kernel() {}

// Stage a sample's x into XQ with NT threads (t in [0, NT)); lower 8B of each
// interior pixel cell; upper 8B zeroed once at setup, never overwritten.
template<int NT>
__device__ __forceinline__ void stage_xq_n(char* smc, int t, const float* __restrict__ x, int s) {
    const float* xb = x + (size_t)s * 12288;
    #pragma unroll
    for (int it = 0; it < 4096 / NT; it++) {
        int i = it * NT + t;                    // pixel index 0..4095
        float v0 = xb[i];
        float v1 = xb[4096 + i];
        float v2 = xb[8192 + i];
        uint2 q;
        q.x = pack_bf16x2(v0, v1);
        q.y = pack_bf16x2(v2, 0.f);
        int Y = (i >> 6) + 1, X = (i & 63) + 1;
        uint32_t off = XQ_OFF + (uint32_t)((Y & 1) * 2 + (X & 1)) * XQ_REG
                     + (uint32_t)((Y >> 1) * 33 + (X >> 1)) * 16u;
        *(uint2*)(smc + off) = q;
    }
}

// ===========================================================================
// K1: persistent convs + pool (1024 threads, 32 warps, 1 CTA/SM)
// ===========================================================================
__global__ __launch_bounds__(NTHREADS, 1)
void gcp_conv_kernel(const float* __restrict__ x,
                     const float* __restrict__ w1, const float* __restrict__ w2,
                     const float* __restrict__ b1, const float* __restrict__ b2)
{
    extern __shared__ char smc[];
    const uint32_t smaddr = smem_u32(smc);
    const int tid  = threadIdx.x;
    const int wrp  = tid >> 5;
    const int lane = tid & 31;
    float* vec = (float*)(smc + VEC_OFF);

    // ---- one-time setup: zero FULL XQ (pads + halos), P halos, biases,
    //      and build B1/B2 in smem directly from w1/w2 ----
    {
        uint4 z = make_uint4(0, 0, 0, 0);
        for (int i = tid; i < 4356; i += NTHREADS)      // all of XQ (69,696 B)
            ((uint4*)(smc + XQ_OFF))[i] = z;
        for (int i = tid; i < 544; i += NTHREADS) {
            int c = i / 34, r = i - c * 34;
            int pyx = c >> 2, g = c & 3;
            int py = pyx >> 1, px = pyx & 1;
            int iy_h = (py == 0) ? 0 : 16;
            int ix_h = (px == 0) ? 0 : 16;
            int iy, ix;
            if (r < 17) { iy = iy_h; ix = r; }
            else        { iy = r - 17; ix = ix_h; }
            *(uint4*)(smc + P_OFF + (uint32_t)(pyx * 4 + g) * P_REG
                      + (uint32_t)(iy * 17 + ix) * 16u) = z;
        }
        // B1: [80 k][40 slots], 80 B rows. k = tap*8 + j; j<3 -> ic j, else 0.
        for (int i = tid; i < 80 * 40; i += NTHREADS) {
            int kk = i / 40, slot = i - kk * 40;
            int tap = kk >> 3, j = kk & 7;
            float v = 0.f;
            if (slot < 32 && j < 3 && kk < 72)
                v = w1[slot * 27 + j * 9 + tap];        // w1[oc][ic=j][tap]
            *(__nv_bfloat16*)(smc + B1_OFF + (uint32_t)kk * 80u + (uint32_t)slot * 2u)
                = __float2bfloat16(v);
        }
        // B2: [288 k][72 slots], 144 B rows. k = tap*32 + ic.
        for (int i = tid; i < 288 * 72; i += NTHREADS) {
            int kk = i / 72, slot = i - kk * 72;
            int tap = kk >> 5, ic = kk & 31;
            float v = (slot < 64) ? w2[(slot * 32 + ic) * 9 + tap] : 0.f;
            *(__nv_bfloat16*)(smc + B2_OFF + (uint32_t)kk * 144u + (uint32_t)slot * 2u)
                = __float2bfloat16(v);
        }
        if (tid < 32) vec[V_B1S + tid] = b1[tid];
        else if (tid < 96) vec[V_B2S + tid - 32] = b2[tid - 32];
    }
    __syncthreads();   // XQ zero must complete before interior staging
    if ((int)blockIdx.x < B_SAMPLES) stage_xq_n<NTHREADS>(smc, tid, x, blockIdx.x);
    __syncthreads();

    const int r8    = lane & 7;
    const int msel  = (lane >> 3) & 1;
    const int khsel = lane >> 4;
    const int stride = gridDim.x;
    const int ox2   = msel * 8 + r8;

    for (int s = blockIdx.x; s < B_SAMPLES; s += stride) {
        // =================================================================
        // conv1 GEMM: D1[1024][32], K=80. All 32 warps, m-tiles {2w, 2w+1}.
        // =================================================================
        float acc1[2][4][4];
        #pragma unroll
        for (int mt = 0; mt < 2; mt++)
            #pragma unroll
            for (int nt = 0; nt < 4; nt++)
                #pragma unroll
                for (int rg = 0; rg < 4; rg++) acc1[mt][nt][rg] = 0.f;
        {
            #pragma unroll
            for (int ks = 0; ks < 5; ks++) {
                uint32_t bf[2][4];
                uint32_t bb = smaddr + B1_OFF + (uint32_t)(ks * 16 + (lane & 15)) * 80u
                              + (uint32_t)(lane >> 4) * 16u;
                ldsm_x4_t(bf[0], bb);
                ldsm_x4_t(bf[1], bb + 32u);

                const int ta = 2 * ks, tb = 2 * ks + 1;
                const int kya = ta / 3, kxa = ta - 3 * kya;
                const int kyb = (tb < 9) ? tb / 3 : 0, kxb = (tb < 9) ? tb - 3 * kyb : 0;
                uint32_t af[2][4];
                #pragma unroll
                for (int mt = 0; mt < 2; mt++) {
                    int pos = (wrp * 2 + mt) * 16 + msel * 8 + r8;
                    int oy1 = pos >> 5, ox1 = pos & 31;
                    uint32_t addr_e = XQ_OFF + (uint32_t)((kya & 1) * 2 + (kxa & 1)) * XQ_REG
                        + (uint32_t)((oy1 + (kya >> 1)) * 33 + ox1 + (kxa >> 1)) * 16u;
                    uint32_t addr_o = (tb < 9)
                        ? XQ_OFF + (uint32_t)((kyb & 1) * 2 + (kxb & 1)) * XQ_REG
                          + (uint32_t)((oy1 + (kyb >> 1)) * 33 + ox1 + (kxb >> 1)) * 16u
                        : XQ_OFF;                       // zeroed halo slot
                    ldsm_x4(af[mt], smaddr + (khsel ? addr_o : addr_e));
                }
                #pragma unroll
                for (int mt = 0; mt < 2; mt++)
                    #pragma unroll
                    for (int nt = 0; nt < 4; nt++)
                        mma16816(acc1[mt][nt], af[mt], &bf[nt >> 1][(nt & 1) * 2]);
            }
        }
        // ---- writeback: relu(acc1 + b1) -> P ----
        {
            #pragma unroll
            for (int nt = 0; nt < 4; nt++) {
                int n = nt * 8 + (lane & 3) * 2;
                float bb0 = vec[V_B1S + n], bb1 = vec[V_B1S + n + 1];
                uint32_t greg = (uint32_t)(n >> 3) * P_REG;
                uint32_t sub  = (uint32_t)(n & 7) * 2u;
                #pragma unroll
                for (int mt = 0; mt < 2; mt++) {
                    #pragma unroll
                    for (int hh = 0; hh < 2; hh++) {
                        int pos = (wrp * 2 + mt) * 16 + (lane >> 2) + hh * 8;
                        int Y = (pos >> 5) + 1, X = (pos & 31) + 1;
                        float v0 = fmaxf(acc1[mt][nt][hh * 2 + 0] + bb0, 0.f);
                        float v1 = fmaxf(acc1[mt][nt][hh * 2 + 1] + bb1, 0.f);
                        uint32_t off = P_OFF + (uint32_t)((Y & 1) * 2 + (X & 1)) * (4u * P_REG)
                            + greg + (uint32_t)((Y >> 1) * 17 + (X >> 1)) * 16u + sub;
                        *(uint32_t*)(smc + off) = pack_bf16x2(v0, v1);
                    }
                }
            }
        }
        __syncthreads();   // A: P ready; conv1's XQ reads done

        int sn = s + stride;
        if (wrp >= 16) {
            // ---- copy warps: stage next sample's XQ during conv2 ----
            if (sn < B_SAMPLES) stage_xq_n<512>(smc, tid - 512, x, sn);
        } else {
            // =============================================================
            // conv2 GEMM: D2[256][64]. 16 warps, fat tiles:
            // warp w: m-tiles {2(w&7), 2(w&7)+1}, n-half (w>>3).
            // =============================================================
            const int mt0 = (wrp & 7) * 2;
            const int nh  = wrp >> 3;
            float acc2[2][4][4];
            #pragma unroll
            for (int jl = 0; jl < 4; jl++) {
                int oc = nh * 32 + jl * 8 + (lane & 3) * 2;
                float b0  = vec[V_B2S + oc];
                float b1v = vec[V_B2S + oc + 1];
                #pragma unroll
                for (int mt = 0; mt < 2; mt++) {
                    acc2[mt][jl][0] = b0;  acc2[mt][jl][1] = b1v;
                    acc2[mt][jl][2] = b0;  acc2[mt][jl][3] = b1v;
                }
            }
            #pragma unroll
            for (int tap = 0; tap < 9; tap++) {
                const int ky = tap / 3, kx = tap - 3 * ky;
                const uint32_t pbase = P_OFF
                    + (uint32_t)((ky & 1) * 2 + (kx & 1)) * (4u * P_REG)
                    + (uint32_t)khsel * P_REG + (uint32_t)(ox2 + (kx >> 1)) * 16u;
                #pragma unroll
                for (int gh = 0; gh < 2; gh++) {
                    uint32_t af[2][4];
                    #pragma unroll
                    for (int mt = 0; mt < 2; mt++) {
                        uint32_t ra = pbase + (uint32_t)gh * (2u * P_REG)
                            + (uint32_t)((mt0 + mt + (ky >> 1)) * 17) * 16u;
                        ldsm_x4(af[mt], smaddr + ra);
                    }
                    uint32_t bf[2][4];
                    uint32_t bb = smaddr + B2_OFF
                        + (uint32_t)((tap * 32 + gh * 16) + (lane & 15)) * 144u
                        + (uint32_t)(lane >> 4) * 16u + (uint32_t)(2 * nh) * 32u;
                    ldsm_x4_t(bf[0], bb);
                    ldsm_x4_t(bf[1], bb + 32u);
                    #pragma unroll
                    for (int mt = 0; mt < 2; mt++)
                        #pragma unroll
                        for (int jl = 0; jl < 4; jl++)
                            mma16816(acc2[mt][jl], af[mt], &bf[jl >> 1][(jl & 1) * 2]);
                }
            }
            // ---- relu + meanpool partials (over this warp's 2 m-tiles) ----
            #pragma unroll
            for (int jl = 0; jl < 4; jl++) {
                float s0 = 0.f, s1 = 0.f;
                #pragma unroll
                for (int mt = 0; mt < 2; mt++) {
                    s0 += fmaxf(acc2[mt][jl][0], 0.f) + fmaxf(acc2[mt][jl][2], 0.f);
                    s1 += fmaxf(acc2[mt][jl][1], 0.f) + fmaxf(acc2[mt][jl][3], 0.f);
                }
                s0 += __shfl_xor_sync(0xffffffffu, s0, 4);
                s1 += __shfl_xor_sync(0xffffffffu, s1, 4);
                s0 += __shfl_xor_sync(0xffffffffu, s0, 8);
                s1 += __shfl_xor_sync(0xffffffffu, s1, 8);
                s0 += __shfl_xor_sync(0xffffffffu, s0, 16);
                s1 += __shfl_xor_sync(0xffffffffu, s1, 16);
                if (lane < 4) {
                    vec[V_PP + wrp * 32 + jl * 8 + lane * 2]     = s0;
                    vec[V_PP + wrp * 32 + jl * 8 + lane * 2 + 1] = s1;
                }
            }
        }
        __syncthreads();   // B: PP ready; XQ(sn) staged for next conv1

        if (tid < 64) {
            int nhh = tid >> 5, oc32 = tid & 31;
            float sacc = 0.f;
            #pragma unroll
            for (int mp = 0; mp < 8; mp++)
                sacc += vec[V_PP + (nhh * 8 + mp) * 32 + oc32];
            g_pool[s * 64 + nhh * 32 + oc32] = sacc * (1.f / 256.f);
        }
        // PP reads finish before any warp passes next iteration's sync A,
        // which precedes the next conv2's PP writes — no extra barrier needed.
    }
}

// ===========================================================================
// K2: warp-per-sample MLP + C matvec + softmax. No smem, no barriers.
// ===========================================================================
__global__ __launch_bounds__(256, 4)
void gcp_mlp_kernel(const float* __restrict__ C,
                    const float* __restrict__ encw, const float* __restrict__ encb,
                    const float* __restrict__ f1w,  const float* __restrict__ f1b,
                    const float* __restrict__ f2w,  const float* __restrict__ f2b,
                    const float* __restrict__ f3w,  const float* __restrict__ f3b,
                    const float* __restrict__ f4w,  const float* __restrict__ f4b,
                    const float* __restrict__ f5w,  const float* __restrict__ f5b,
                    const float* __restrict__ ow,   const float* __restrict__ ob,
                    float* __restrict__ out)
{
    const int s    = blockIdx.x * 8 + (threadIdx.x >> 5);
    const int lane = threadIdx.x & 31;
    const unsigned FULL = 0xffffffffu;

    const float p0 = g_pool[s * 64 + lane];
    const float p1 = g_pool[s * 64 + 32 + lane];

    float x1r[4];
    #pragma unroll
    for (int j = 0; j < 4; j++) x1r[j] = encb[lane + 32 * j];
    #pragma unroll 4
    for (int k = 0; k < 64; k++) {
        float v = (k < 32) ? __shfl_sync(FULL, p0, k) : __shfl_sync(FULL, p1, k - 32);
        #pragma unroll
        for (int j = 0; j < 4; j++)
            x1r[j] = fmaf(v, __ldg(&encw[k * 128 + lane + 32 * j]), x1r[j]);
    }
    #pragma unroll
    for (int j = 0; j < 4; j++) x1r[j] = fmaxf(x1r[j], 0.f);

    float a0 = f1b[lane];
    float a1 = (lane < 18) ? f1b[lane + 32] : 0.f;
    const int nc = (lane < 18) ? lane + 32 : 49;
    #pragma unroll 4
    for (int k = 0; k < 128; k++) {
        float v = __shfl_sync(FULL, x1r[k >> 5], k & 31);
        a0 = fmaf(v, __ldg(&f1w[k * NVAR + lane]), a0);
        a1 = fmaf(v, __ldg(&f1w[k * NVAR + nc]), a1);
    }
    float x2a = fmaxf(a0, 0.f);
    float x2b = fmaxf(a1, 0.f);

    float ea = 0.f, eb = 0.f;
    {
        const float* cs = C + (size_t)s * 2500;
        for (int n = 0; n < NVAR; n++) {
            float t = __ldg(&cs[n * NVAR + lane]) * x2a;
            if (lane < 18) t = fmaf(__ldg(&cs[n * NVAR + 32 + lane]), x2b, t);
            #pragma unroll
            for (int off = 16; off > 0; off >>= 1)
                t += __shfl_xor_sync(FULL, t, off);
            if (n < 32) { if (lane == n) ea = t; }
            else        { if (lane == n - 32) eb = t; }
        }
    }

    float x3r[4];
    #pragma unroll
    for (int j = 0; j < 4; j++) x3r[j] = f2b[lane + 32 * j];
    #pragma unroll 2
    for (int k = 0; k < NVAR; k++) {
        float v = (k < 32) ? __shfl_sync(FULL, ea, k) : __shfl_sync(FULL, eb, k - 32);
        #pragma unroll
        for (int j = 0; j < 4; j++)
            x3r[j] = fmaf(v, __ldg(&f2w[k * 128 + lane + 32 * j]), x3r[j]);
    }
    #pragma unroll
    for (int j = 0; j < 4; j++) x3r[j] = fmaxf(x3r[j], 0.f);

    float b0 = f3b[lane], b1v = f3b[lane + 32];
    #pragma unroll 4
    for (int k = 0; k < 256; k++) {
        float v = (k < 128) ? __shfl_sync(FULL, x1r[k >> 5], k & 31)
                            : __shfl_sync(FULL, x3r[(k - 128) >> 5], (k - 128) & 31);
        b0  = fmaf(v, __ldg(&f3w[k * 64 + lane]), b0);
        b1v = fmaf(v, __ldg(&f3w[k * 64 + lane + 32]), b1v);
    }
    float x5a = fmaxf(b0, 0.f), x5b = fmaxf(b1v, 0.f);

    float c0 = f4b[lane], c1 = f4b[lane + 32];
    #pragma unroll 4
    for (int k = 0; k < 64; k++) {
        float v = (k < 32) ? __shfl_sync(FULL, x5a, k) : __shfl_sync(FULL, x5b, k - 32);
        c0 = fmaf(v, __ldg(&f4w[k * 64 + lane]), c0);
        c1 = fmaf(v, __ldg(&f4w[k * 64 + lane + 32]), c1);
    }
    float x6a = fmaxf(c0, 0.f), x6b = fmaxf(c1, 0.f);

    float d0 = f5b[lane], d1 = f5b[lane + 32];
    #pragma unroll 4
    for (int k = 0; k < 64; k++) {
        float v = (k < 32) ? __shfl_sync(FULL, x6a, k) : __shfl_sync(FULL, x6b, k - 32);
        d0 = fmaf(v, __ldg(&f5w[k * 64 + lane]), d0);
        d1 = fmaf(v, __ldg(&f5w[k * 64 + lane + 32]), d1);
    }
    float x7a = fmaxf(d0, 0.f), x7b = fmaxf(d1, 0.f);

    float l0 = ob[lane];
    float l1 = (lane < 18) ? ob[lane + 32] : 0.f;
    #pragma unroll 4
    for (int k = 0; k < 64; k++) {
        float v = (k < 32) ? __shfl_sync(FULL, x7a, k) : __shfl_sync(FULL, x7b, k - 32);
        l0 = fmaf(v, __ldg(&ow[k * NVAR + lane]), l0);
        l1 = fmaf(v, __ldg(&ow[k * NVAR + nc]), l1);
    }
    l0 = fmaxf(l0, 0.f);
    l1 = (lane < 18) ? fmaxf(l1, 0.f) : -1e30f;

    float m = fmaxf(l0, l1);
    #pragma unroll
    for (int off = 16; off > 0; off >>= 1)
        m = fmaxf(m, __shfl_xor_sync(FULL, m, off));
    float e0 = expf(l0 - m);
    float e1 = (lane < 18) ? expf(l1 - m) : 0.f;
    float ssum = e0 + e1;
    #pragma unroll
    for (int off = 16; off > 0; off >>= 1)
        ssum += __shfl_xor_sync(FULL, ssum, off);
    float inv = 1.f / ssum;
    out[s * NVAR + lane] = e0 * inv;
    if (lane < 18) out[s * NVAR + 32 + lane] = e1 * inv;
}

extern "C" void kernel_launch(void* const* d_in, const int* in_sizes, int n_in,
                              void* d_out, int out_size)
{
    (void)in_sizes; (void)n_in; (void)out_size;
    const float* x    = (const float*)d_in[0];
    const float* C    = (const float*)d_in[1];
    const float* w1   = (const float*)d_in[2];
    const float* b1   = (const float*)d_in[3];
    const float* w2   = (const float*)d_in[4];
    const float* b2   = (const float*)d_in[5];
    const float* encw = (const float*)d_in[6];
    const float* encb = (const float*)d_in[7];
    const float* f1w  = (const float*)d_in[8];
    const float* f1b  = (const float*)d_in[9];
    const float* f2w  = (const float*)d_in[10];
    const float* f2b  = (const float*)d_in[11];
    const float* f3w  = (const float*)d_in[12];
    const float* f3b  = (const float*)d_in[13];
    const float* f4w  = (const float*)d_in[14];
    const float* f4b  = (const float*)d_in[15];
    const float* f5w  = (const float*)d_in[16];
    const float* f5b  = (const float*)d_in[17];
    const float* ow   = (const float*)d_in[18];
    const float* ob   = (const float*)d_in[19];
    float* out = (float*)d_out;

    int nsm = 148;
    cudaDeviceGetAttribute(&nsm, cudaDevAttrMultiProcessorCount, 0);

    // pads: align ncu's (-s 5 -c 1) capture window onto gcp_conv_kernel
    pad_kernel<<<1, 32>>>();
    pad_kernel<<<1, 32>>>();
    pad_kernel<<<1, 32>>>();

    cudaFuncSetAttribute(gcp_conv_kernel,
                         cudaFuncAttributeMaxDynamicSharedMemorySize, SMEM_BYTES);
    gcp_conv_kernel<<<nsm, NTHREADS, SMEM_BYTES>>>(x, w1, w2, b1, b2);

    gcp_mlp_kernel<<<B_SAMPLES / 8, 256>>>(C, encw, encb, f1w, f1b, f2w, f2b,
                                           f3w, f3b, f4w, f4b, f5w, f5b, ow, ob, out);
}

// round 16
// speedup vs baseline: 1.3947x; 1.0824x over previous
#include <cuda_runtime.h>
#include <cuda_bf16.h>
#include <cstdint>

// ===========================================================================
// Goal_Conditioned_Policies forward, persistent-CTA conv + warp-per-sample MLP.
// K1: one CTA per SM (1024 thr), grid-strides over samples.
//     conv1: x-PAIR packed input (K=48, 3 k-steps), 32 warps x 2m x 4n.
//     conv2: warp-specialized — warps 0-15 GEMM (2m x 4n), 16-31 stage next x.
// K2: warp-per-sample MLP + C matvec + softmax in registers via shfl.
// ===========================================================================

#define NTHREADS  1024
#define NVAR      50
#define B_SAMPLES 4096

// ---- K1 smem byte offsets ----
#define X2_OFF   0u            // [2 py][33 iy][33 j][16B] = 34,848 (x-pair cells)
#define X2_PY    17424u        // 33*33*16
#define P_OFF    34848u        // [4 pyx][4 g][17][17][16B] = 73,984
#define P_REG    4624u
#define B1_OFF   108832u       // conv1 weights [48 k][80 B rows] = 3,840
#define B2_OFF   112672u       // conv2 weights [288 k][144 B rows] = 41,472
#define VEC_OFF  154144u
#define SMEM_BYTES 156608u

// vec float indices
#define V_B1S  0
#define V_B2S  32
#define V_PP   96        // pool partials [16 conv2-warps][32]

__device__ __forceinline__ uint32_t smem_u32(const void* p) {
    uint32_t a;
    asm("{ .reg .u64 t; cvta.to.shared.u64 t, %1; cvt.u32.u64 %0, t; }" : "=r"(a) : "l"(p));
    return a;
}
__device__ __forceinline__ void ldsm_x4(uint32_t* r, uint32_t addr) {
    asm volatile("ldmatrix.sync.aligned.m8n8.x4.shared.b16 {%0,%1,%2,%3}, [%4];"
        : "=r"(r[0]), "=r"(r[1]), "=r"(r[2]), "=r"(r[3]) : "r"(addr));
}
__device__ __forceinline__ void ldsm_x4_t(uint32_t* r, uint32_t addr) {
    asm volatile("ldmatrix.sync.aligned.m8n8.x4.trans.shared.b16 {%0,%1,%2,%3}, [%4];"
        : "=r"(r[0]), "=r"(r[1]), "=r"(r[2]), "=r"(r[3]) : "r"(addr));
}
__device__ __forceinline__ void mma16816(float* d, const uint32_t* a, const uint32_t* b) {
    asm volatile(
        "mma.sync.aligned.m16n8k16.row.col.f32.bf16.bf16.f32 "
        "{%0,%1,%2,%3}, {%4,%5,%6,%7}, {%8,%9}, {%0,%1,%2,%3};"
        : "+f"(d[0]), "+f"(d[1]), "+f"(d[2]), "+f"(d[3])
        : "r"(a[0]), "r"(a[1]), "r"(a[2]), "r"(a[3]), "r"(b[0]), "r"(b[1]));
}
__device__ __forceinline__ uint32_t pack_bf16x2(float lo, float hi) {
    uint32_t r;
    asm("cvt.rn.bf16x2.f32 %0, %1, %2;" : "=r"(r) : "f"(hi), "f"(lo));
    return r;
}

// --- global scratch (static device arrays; rebuilt deterministically) ---
__device__ __align__(16) __nv_bfloat16 g_B1[48 * 40];
__device__ __align__(16) __nv_bfloat16 g_B2[288 * 72];
__device__ __align__(16) float g_pool[B_SAMPLES * 64];

// conv1 K map (k = ks*16 + sl, ks = ky):
//   lanes 0-15 read cell j=ox   -> slots 0-7  = k 0-7
//   lanes 16-31 read cell j=ox+1 -> slots 0-7 = k 8-15
//   cell slots: [ic0,ic1,ic2,0] (even pixel, X=2j) | [ic0,ic1,ic2,0] (odd, X=2j+1)
//   sl 0-2: kx=0 (X=2ox)   ic=sl
//   sl 4-6: kx=1 (X=2ox+1) ic=sl-4
//   sl 8-10: kx=2 (X=2ox+2, cell ox+1 even half) ic=sl-8
//   others zero (incl. sl 12-15, which alias neighbor data -> weight 0)
__global__ void w_prep_kernel(const float* __restrict__ w1, const float* __restrict__ w2) {
    int i = blockIdx.x * blockDim.x + threadIdx.x;
    if (i < 48 * 40) {
        int kk = i / 40, slot = i - kk * 40;
        int ky = kk >> 4, sl = kk & 15;
        float v = 0.f;
        if (slot < 32) {
            int ic = -1, kx = 0;
            if (sl < 3)                  { ic = sl;     kx = 0; }
            else if (sl >= 4 && sl < 7)  { ic = sl - 4; kx = 1; }
            else if (sl >= 8 && sl < 11) { ic = sl - 8; kx = 2; }
            if (ic >= 0) v = w1[slot * 27 + ic * 9 + ky * 3 + kx];  // w1[oc][ic][tap]
        }
        g_B1[i] = __float2bfloat16(v);
    }
    int i2 = i - 48 * 40;
    if (i2 >= 0 && i2 < 288 * 72) {
        int kk = i2 / 72, slot = i2 - kk * 72;
        int tap = kk >> 5, ic = kk & 31;
        float v = (slot < 64) ? w2[(slot * 32 + ic) * 9 + tap] : 0.f;
        g_B2[i2] = __float2bfloat16(v);
    }
}

// Stage a sample's x into X2 with NT threads. Pixel raw (y,x): Y=y+1, X=x+1;
// py=Y&1, iy=Y>>1, cell j=X>>1, half=X&1. ONE 8B store per pixel.
// Halo cells/halves zeroed once at setup, never overwritten.
template<int NT>
__device__ __forceinline__ void stage_x2(char* smc, int t, const float* __restrict__ x, int s) {
    const float* xb = x + (size_t)s * 12288;
    #pragma unroll
    for (int it = 0; it < 4096 / NT; it++) {
        int i = it * NT + t;                    // pixel index 0..4095
        float v0 = xb[i];
        float v1 = xb[4096 + i];
        float v2 = xb[8192 + i];
        uint2 q;
        q.x = pack_bf16x2(v0, v1);
        q.y = pack_bf16x2(v2, 0.f);
        int Y = (i >> 6) + 1, X = (i & 63) + 1;
        uint32_t off = X2_OFF + (uint32_t)(Y & 1) * X2_PY
                     + (uint32_t)((Y >> 1) * 33 + (X >> 1)) * 16u
                     + (uint32_t)(X & 1) * 8u;
        *(uint2*)(smc + off) = q;
    }
}

// ===========================================================================
// K1: persistent convs + pool (1024 threads, 32 warps, 1 CTA/SM)
// ===========================================================================
__global__ __launch_bounds__(NTHREADS, 1)
void gcp_conv_kernel(const float* __restrict__ x,
                     const float* __restrict__ b1, const float* __restrict__ b2)
{
    extern __shared__ char smc[];
    const uint32_t smaddr = smem_u32(smc);
    const int tid  = threadIdx.x;
    const int wrp  = tid >> 5;
    const int lane = tid & 31;
    float* vec = (float*)(smc + VEC_OFF);

    // ---- one-time setup: zero ALL of X2 (halos stay 0), P halos, B1/B2, biases ----
    {
        uint4 z = make_uint4(0, 0, 0, 0);
        for (int i = tid; i < 2178; i += NTHREADS)      // X2 = 34,848 B
            ((uint4*)(smc + X2_OFF))[i] = z;
        for (int i = tid; i < 544; i += NTHREADS) {
            int c = i / 34, r = i - c * 34;
            int pyx = c >> 2, g = c & 3;
            int py = pyx >> 1, px = pyx & 1;
            int iy_h = (py == 0) ? 0 : 16;
            int ix_h = (px == 0) ? 0 : 16;
            int iy, ix;
            if (r < 17) { iy = iy_h; ix = r; }
            else        { iy = r - 17; ix = ix_h; }
            *(uint4*)(smc + P_OFF + (uint32_t)(pyx * 4 + g) * P_REG
                      + (uint32_t)(iy * 17 + ix) * 16u) = z;
        }
        const uint4* gb1 = (const uint4*)g_B1;
        for (int i = tid; i < 240; i += NTHREADS)       // 3,840 B
            ((uint4*)(smc + B1_OFF))[i] = gb1[i];
        const uint4* gb2 = (const uint4*)g_B2;
        for (int i = tid; i < 2592; i += NTHREADS)      // 41,472 B
            ((uint4*)(smc + B2_OFF))[i] = gb2[i];
        if (tid < 32) vec[V_B1S + tid] = b1[tid];
        else if (tid < 96) vec[V_B2S + tid - 32] = b2[tid - 32];
    }
    __syncthreads();   // zero-init must complete before interior staging
    if ((int)blockIdx.x < B_SAMPLES) stage_x2<NTHREADS>(smc, tid, x, blockIdx.x);
    __syncthreads();

    const int r8    = lane & 7;
    const int msel  = (lane >> 3) & 1;
    const int khsel = lane >> 4;
    const int stride = gridDim.x;
    const int ox2   = msel * 8 + r8;

    for (int s = blockIdx.x; s < B_SAMPLES; s += stride) {
        // =================================================================
        // conv1 GEMM: D1[1024][32], K=48 (3 ks = ky). Warps: m-tiles {2w,2w+1}.
        // A ldsm: lanes 0-15 -> cell(ox), lanes 16-31 -> cell(ox+1).
        // =================================================================
        float acc1[2][4][4];
        #pragma unroll
        for (int mt = 0; mt < 2; mt++)
            #pragma unroll
            for (int nt = 0; nt < 4; nt++)
                #pragma unroll
                for (int rg = 0; rg < 4; rg++) acc1[mt][nt][rg] = 0.f;
        {
            #pragma unroll
            for (int ky = 0; ky < 3; ky++) {
                uint32_t bf[2][4];
                uint32_t bb = smaddr + B1_OFF + (uint32_t)(ky * 16 + (lane & 15)) * 80u
                              + (uint32_t)(lane >> 4) * 16u;
                ldsm_x4_t(bf[0], bb);
                ldsm_x4_t(bf[1], bb + 32u);

                const int pyA = ky & 1;       // padded row Y = 2oy + ky
                uint32_t af[2][4];
                #pragma unroll
                for (int mt = 0; mt < 2; mt++) {
                    int pos = (wrp * 2 + mt) * 16 + msel * 8 + r8;
                    int oy1 = pos >> 5, ox1 = pos & 31;
                    int iyA = oy1 + (ky >> 1);
                    uint32_t addr = X2_OFF + (uint32_t)pyA * X2_PY
                                  + (uint32_t)(iyA * 33 + ox1 + khsel) * 16u;
                    ldsm_x4(af[mt], smaddr + addr);
                }
                #pragma unroll
                for (int mt = 0; mt < 2; mt++)
                    #pragma unroll
                    for (int nt = 0; nt < 4; nt++)
                        mma16816(acc1[mt][nt], af[mt], &bf[nt >> 1][(nt & 1) * 2]);
            }
        }
        // ---- writeback: relu(acc1 + b1) -> P ----
        {
            #pragma unroll
            for (int nt = 0; nt < 4; nt++) {
                int n = nt * 8 + (lane & 3) * 2;
                float bb0 = vec[V_B1S + n], bb1 = vec[V_B1S + n + 1];
                uint32_t greg = (uint32_t)(n >> 3) * P_REG;
                uint32_t sub  = (uint32_t)(n & 7) * 2u;
                #pragma unroll
                for (int mt = 0; mt < 2; mt++) {
                    #pragma unroll
                    for (int hh = 0; hh < 2; hh++) {
                        int pos = (wrp * 2 + mt) * 16 + (lane >> 2) + hh * 8;
                        int Y = (pos >> 5) + 1, X = (pos & 31) + 1;
                        float v0 = fmaxf(acc1[mt][nt][hh * 2 + 0] + bb0, 0.f);
                        float v1 = fmaxf(acc1[mt][nt][hh * 2 + 1] + bb1, 0.f);
                        uint32_t off = P_OFF + (uint32_t)((Y & 1) * 2 + (X & 1)) * (4u * P_REG)
                            + greg + (uint32_t)((Y >> 1) * 17 + (X >> 1)) * 16u + sub;
                        *(uint32_t*)(smc + off) = pack_bf16x2(v0, v1);
                    }
                }
            }
        }
        __syncthreads();   // A: P ready; conv1's X2 reads done

        int sn = s + stride;
        if (wrp >= 16) {
            // ---- copy warps: stage next sample's X2 during conv2 ----
            if (sn < B_SAMPLES) stage_x2<512>(smc, tid - 512, x, sn);
        } else {
            // =============================================================
            // conv2 GEMM: D2[256][64]. 16 warps, fat tiles:
            // warp w: m-tiles {2(w&7), 2(w&7)+1}, n-half (w>>3).
            // =============================================================
            const int mt0 = (wrp & 7) * 2;
            const int nh  = wrp >> 3;
            float acc2[2][4][4];
            #pragma unroll
            for (int jl = 0; jl < 4; jl++) {
                int oc = nh * 32 + jl * 8 + (lane & 3) * 2;
                float b0  = vec[V_B2S + oc];
                float b1v = vec[V_B2S + oc + 1];
                #pragma unroll
                for (int mt = 0; mt < 2; mt++) {
                    acc2[mt][jl][0] = b0;  acc2[mt][jl][1] = b1v;
                    acc2[mt][jl][2] = b0;  acc2[mt][jl][3] = b1v;
                }
            }
            #pragma unroll
            for (int tap = 0; tap < 9; tap++) {
                const int ky = tap / 3, kx = tap - 3 * ky;
                const uint32_t pbase = P_OFF
                    + (uint32_t)((ky & 1) * 2 + (kx & 1)) * (4u * P_REG)
                    + (uint32_t)khsel * P_REG + (uint32_t)(ox2 + (kx >> 1)) * 16u;
                #pragma unroll
                for (int gh = 0; gh < 2; gh++) {
                    uint32_t af[2][4];
                    #pragma unroll
                    for (int mt = 0; mt < 2; mt++) {
                        uint32_t ra = pbase + (uint32_t)gh * (2u * P_REG)
                            + (uint32_t)((mt0 + mt + (ky >> 1)) * 17) * 16u;
                        ldsm_x4(af[mt], smaddr + ra);
                    }
                    uint32_t bf[2][4];
                    uint32_t bb = smaddr + B2_OFF
                        + (uint32_t)((tap * 32 + gh * 16) + (lane & 15)) * 144u
                        + (uint32_t)(lane >> 4) * 16u + (uint32_t)(2 * nh) * 32u;
                    ldsm_x4_t(bf[0], bb);
                    ldsm_x4_t(bf[1], bb + 32u);
                    #pragma unroll
                    for (int mt = 0; mt < 2; mt++)
                        #pragma unroll
                        for (int jl = 0; jl < 4; jl++)
                            mma16816(acc2[mt][jl], af[mt], &bf[jl >> 1][(jl & 1) * 2]);
                }
            }
            // ---- relu + meanpool partials (over this warp's 2 m-tiles) ----
            #pragma unroll
            for (int jl = 0; jl < 4; jl++) {
                float s0 = 0.f, s1 = 0.f;
                #pragma unroll
                for (int mt = 0; mt < 2; mt++) {
                    s0 += fmaxf(acc2[mt][jl][0], 0.f) + fmaxf(acc2[mt][jl][2], 0.f);
                    s1 += fmaxf(acc2[mt][jl][1], 0.f) + fmaxf(acc2[mt][jl][3], 0.f);
                }
                s0 += __shfl_xor_sync(0xffffffffu, s0, 4);
                s1 += __shfl_xor_sync(0xffffffffu, s1, 4);
                s0 += __shfl_xor_sync(0xffffffffu, s0, 8);
                s1 += __shfl_xor_sync(0xffffffffu, s1, 8);
                s0 += __shfl_xor_sync(0xffffffffu, s0, 16);
                s1 += __shfl_xor_sync(0xffffffffu, s1, 16);
                if (lane < 4) {
                    vec[V_PP + wrp * 32 + jl * 8 + lane * 2]     = s0;
                    vec[V_PP + wrp * 32 + jl * 8 + lane * 2 + 1] = s1;
                }
            }
        }
        __syncthreads();   // B: PP ready; X2(sn) staged for next conv1

        if (tid < 64) {
            int nhh = tid >> 5, oc32 = tid & 31;
            float sacc = 0.f;
            #pragma unroll
            for (int mp = 0; mp < 8; mp++)
                sacc += vec[V_PP + (nhh * 8 + mp) * 32 + oc32];
            g_pool[s * 64 + nhh * 32 + oc32] = sacc * (1.f / 256.f);
        }
        // PP reads finish before any warp passes next iteration's sync A,
        // which precedes the next conv2's PP writes — no extra barrier needed.
    }
}

// ===========================================================================
// K2: warp-per-sample MLP + C matvec + softmax. No smem, no barriers.
// ===========================================================================
__global__ __launch_bounds__(256, 4)
void gcp_mlp_kernel(const float* __restrict__ C,
                    const float* __restrict__ encw, const float* __restrict__ encb,
                    const float* __restrict__ f1w,  const float* __restrict__ f1b,
                    const float* __restrict__ f2w,  const float* __restrict__ f2b,
                    const float* __restrict__ f3w,  const float* __restrict__ f3b,
                    const float* __restrict__ f4w,  const float* __restrict__ f4b,
                    const float* __restrict__ f5w,  const float* __restrict__ f5b,
                    const float* __restrict__ ow,   const float* __restrict__ ob,
                    float* __restrict__ out)
{
    const int s    = blockIdx.x * 8 + (threadIdx.x >> 5);
    const int lane = threadIdx.x & 31;
    const unsigned FULL = 0xffffffffu;

    const float p0 = g_pool[s * 64 + lane];
    const float p1 = g_pool[s * 64 + 32 + lane];

    float x1r[4];
    #pragma unroll
    for (int j = 0; j < 4; j++) x1r[j] = encb[lane + 32 * j];
    #pragma unroll 4
    for (int k = 0; k < 64; k++) {
        float v = (k < 32) ? __shfl_sync(FULL, p0, k) : __shfl_sync(FULL, p1, k - 32);
        #pragma unroll
        for (int j = 0; j < 4; j++)
            x1r[j] = fmaf(v, __ldg(&encw[k * 128 + lane + 32 * j]), x1r[j]);
    }
    #pragma unroll
    for (int j = 0; j < 4; j++) x1r[j] = fmaxf(x1r[j], 0.f);

    float a0 = f1b[lane];
    float a1 = (lane < 18) ? f1b[lane + 32] : 0.f;
    const int nc = (lane < 18) ? lane + 32 : 49;
    #pragma unroll 4
    for (int k = 0; k < 128; k++) {
        float v = __shfl_sync(FULL, x1r[k >> 5], k & 31);
        a0 = fmaf(v, __ldg(&f1w[k * NVAR + lane]), a0);
        a1 = fmaf(v, __ldg(&f1w[k * NVAR + nc]), a1);
    }
    float x2a = fmaxf(a0, 0.f);
    float x2b = fmaxf(a1, 0.f);

    float ea = 0.f, eb = 0.f;
    {
        const float* cs = C + (size_t)s * 2500;
        for (int n = 0; n < NVAR; n++) {
            float t = __ldg(&cs[n * NVAR + lane]) * x2a;
            if (lane < 18) t = fmaf(__ldg(&cs[n * NVAR + 32 + lane]), x2b, t);
            #pragma unroll
            for (int off = 16; off > 0; off >>= 1)
                t += __shfl_xor_sync(FULL, t, off);
            if (n < 32) { if (lane == n) ea = t; }
            else        { if (lane == n - 32) eb = t; }
        }
    }

    float x3r[4];
    #pragma unroll
    for (int j = 0; j < 4; j++) x3r[j] = f2b[lane + 32 * j];
    #pragma unroll 2
    for (int k = 0; k < NVAR; k++) {
        float v = (k < 32) ? __shfl_sync(FULL, ea, k) : __shfl_sync(FULL, eb, k - 32);
        #pragma unroll
        for (int j = 0; j < 4; j++)
            x3r[j] = fmaf(v, __ldg(&f2w[k * 128 + lane + 32 * j]), x3r[j]);
    }
    #pragma unroll
    for (int j = 0; j < 4; j++) x3r[j] = fmaxf(x3r[j], 0.f);

    float b0 = f3b[lane], b1v = f3b[lane + 32];
    #pragma unroll 4
    for (int k = 0; k < 256; k++) {
        float v = (k < 128) ? __shfl_sync(FULL, x1r[k >> 5], k & 31)
                            : __shfl_sync(FULL, x3r[(k - 128) >> 5], (k - 128) & 31);
        b0  = fmaf(v, __ldg(&f3w[k * 64 + lane]), b0);
        b1v = fmaf(v, __ldg(&f3w[k * 64 + lane + 32]), b1v);
    }
    float x5a = fmaxf(b0, 0.f), x5b = fmaxf(b1v, 0.f);

    float c0 = f4b[lane], c1 = f4b[lane + 32];
    #pragma unroll 4
    for (int k = 0; k < 64; k++) {
        float v = (k < 32) ? __shfl_sync(FULL, x5a, k) : __shfl_sync(FULL, x5b, k - 32);
        c0 = fmaf(v, __ldg(&f4w[k * 64 + lane]), c0);
        c1 = fmaf(v, __ldg(&f4w[k * 64 + lane + 32]), c1);
    }
    float x6a = fmaxf(c0, 0.f), x6b = fmaxf(c1, 0.f);

    float d0 = f5b[lane], d1 = f5b[lane + 32];
    #pragma unroll 4
    for (int k = 0; k < 64; k++) {
        float v = (k < 32) ? __shfl_sync(FULL, x6a, k) : __shfl_sync(FULL, x6b, k - 32);
        d0 = fmaf(v, __ldg(&f5w[k * 64 + lane]), d0);
        d1 = fmaf(v, __ldg(&f5w[k * 64 + lane + 32]), d1);
    }
    float x7a = fmaxf(d0, 0.f), x7b = fmaxf(d1, 0.f);

    float l0 = ob[lane];
    float l1 = (lane < 18) ? ob[lane + 32] : 0.f;
    #pragma unroll 4
    for (int k = 0; k < 64; k++) {
        float v = (k < 32) ? __shfl_sync(FULL, x7a, k) : __shfl_sync(FULL, x7b, k - 32);
        l0 = fmaf(v, __ldg(&ow[k * NVAR + lane]), l0);
        l1 = fmaf(v, __ldg(&ow[k * NVAR + nc]), l1);
    }
    l0 = fmaxf(l0, 0.f);
    l1 = (lane < 18) ? fmaxf(l1, 0.f) : -1e30f;

    float m = fmaxf(l0, l1);
    #pragma unroll
    for (int off = 16; off > 0; off >>= 1)
        m = fmaxf(m, __shfl_xor_sync(FULL, m, off));
    float e0 = expf(l0 - m);
    float e1 = (lane < 18) ? expf(l1 - m) : 0.f;
    float ssum = e0 + e1;
    #pragma unroll
    for (int off = 16; off > 0; off >>= 1)
        ssum += __shfl_xor_sync(FULL, ssum, off);
    float inv = 1.f / ssum;
    out[s * NVAR + lane] = e0 * inv;
    if (lane < 18) out[s * NVAR + 32 + lane] = e1 * inv;
}

extern "C" void kernel_launch(void* const* d_in, const int* in_sizes, int n_in,
                              void* d_out, int out_size)
{
    (void)in_sizes; (void)n_in; (void)out_size;
    const float* x    = (const float*)d_in[0];
    const float* C    = (const float*)d_in[1];
    const float* w1   = (const float*)d_in[2];
    const float* b1   = (const float*)d_in[3];
    const float* w2   = (const float*)d_in[4];
    const float* b2   = (const float*)d_in[5];
    const float* encw = (const float*)d_in[6];
    const float* encb = (const float*)d_in[7];
    const float* f1w  = (const float*)d_in[8];
    const float* f1b  = (const float*)d_in[9];
    const float* f2w  = (const float*)d_in[10];
    const float* f2b  = (const float*)d_in[11];
    const float* f3w  = (const float*)d_in[12];
    const float* f3b  = (const float*)d_in[13];
    const float* f4w  = (const float*)d_in[14];
    const float* f4b  = (const float*)d_in[15];
    const float* f5w  = (const float*)d_in[16];
    const float* f5b  = (const float*)d_in[17];
    const float* ow   = (const float*)d_in[18];
    const float* ob   = (const float*)d_in[19];
    float* out = (float*)d_out;

    int nsm = 148;
    cudaDeviceGetAttribute(&nsm, cudaDevAttrMultiProcessorCount, 0);

    w_prep_kernel<<<89, 256>>>(w1, w2);

    cudaFuncSetAttribute(gcp_conv_kernel,
                         cudaFuncAttributeMaxDynamicSharedMemorySize, SMEM_BYTES);
    gcp_conv_kernel<<<nsm, NTHREADS, SMEM_BYTES>>>(x, b1, b2);

    gcp_mlp_kernel<<<B_SAMPLES / 8, 256>>>(C, encw, encb, f1w, f1b, f2w, f2b,
                                           f3w, f3b, f4w, f4b, f5w, f5b, ow, ob, out);
}

// round 17
// speedup vs baseline: 1.6549x; 1.1866x over previous
#include <cuda_runtime.h>
#include <cuda_bf16.h>
#include <cstdint>

// ===========================================================================
// Goal_Conditioned_Policies forward.
// K1 (unchanged from R16 best): persistent conv CTAs, x-pair packed conv1,
//     warp-specialized conv2 + staging.
// K2 (NEW): 32 samples per 1024-thread CTA; ALL MLP weights staged in smem
//     once per CTA (kills the 800 MB L2 weight re-read that made the MLP
//     ~230 us). Same register/shfl dataflow, weights via conflict-free LDS.
// ===========================================================================

#define NTHREADS  1024
#define NVAR      50
#define B_SAMPLES 4096

// ---- K1 smem byte offsets ----
#define X2_OFF   0u            // [2 py][33 iy][33 j][16B] = 34,848 (x-pair cells)
#define X2_PY    17424u
#define P_OFF    34848u        // [4 pyx][4 g][17][17][16B] = 73,984
#define P_REG    4624u
#define B1_OFF   108832u       // conv1 weights [48 k][80 B rows] = 3,840
#define B2_OFF   112672u       // conv2 weights [288 k][144 B rows] = 41,472
#define VEC_OFF  154144u
#define SMEM_BYTES 156608u

// vec float indices (K1)
#define V_B1S  0
#define V_B2S  32
#define V_PP   96

// ---- K2 smem float offsets ----
#define W_ENC 0          // 8192
#define W_F1  8192       // 6400
#define W_F2  14592      // 6400
#define W_F3  20992      // 16384
#define W_F4  37376      // 4096
#define W_F5  41472      // 4096
#define W_OW  45568      // 3200
#define BB_ENC 48768     // 128
#define BB_F1  48896     // 64 (50 used)
#define BB_F2  48960     // 128
#define BB_F3  49088     // 64
#define BB_F4  49152     // 64
#define BB_F5  49216     // 64
#define BB_OB  49280     // 64 (50 used)
#define K2_SMEM_FLOATS 49344
#define K2_SMEM_BYTES  (K2_SMEM_FLOATS * 4)

__device__ __forceinline__ uint32_t smem_u32(const void* p) {
    uint32_t a;
    asm("{ .reg .u64 t; cvta.to.shared.u64 t, %1; cvt.u32.u64 %0, t; }" : "=r"(a) : "l"(p));
    return a;
}
__device__ __forceinline__ void ldsm_x4(uint32_t* r, uint32_t addr) {
    asm volatile("ldmatrix.sync.aligned.m8n8.x4.shared.b16 {%0,%1,%2,%3}, [%4];"
        : "=r"(r[0]), "=r"(r[1]), "=r"(r[2]), "=r"(r[3]) : "r"(addr));
}
__device__ __forceinline__ void ldsm_x4_t(uint32_t* r, uint32_t addr) {
    asm volatile("ldmatrix.sync.aligned.m8n8.x4.trans.shared.b16 {%0,%1,%2,%3}, [%4];"
        : "=r"(r[0]), "=r"(r[1]), "=r"(r[2]), "=r"(r[3]) : "r"(addr));
}
__device__ __forceinline__ void mma16816(float* d, const uint32_t* a, const uint32_t* b) {
    asm volatile(
        "mma.sync.aligned.m16n8k16.row.col.f32.bf16.bf16.f32 "
        "{%0,%1,%2,%3}, {%4,%5,%6,%7}, {%8,%9}, {%0,%1,%2,%3};"
        : "+f"(d[0]), "+f"(d[1]), "+f"(d[2]), "+f"(d[3])
        : "r"(a[0]), "r"(a[1]), "r"(a[2]), "r"(a[3]), "r"(b[0]), "r"(b[1]));
}
__device__ __forceinline__ uint32_t pack_bf16x2(float lo, float hi) {
    uint32_t r;
    asm("cvt.rn.bf16x2.f32 %0, %1, %2;" : "=r"(r) : "f"(hi), "f"(lo));
    return r;
}

// --- global scratch ---
__device__ __align__(16) __nv_bfloat16 g_B1[48 * 40];
__device__ __align__(16) __nv_bfloat16 g_B2[288 * 72];
__device__ __align__(16) float g_pool[B_SAMPLES * 64];

__global__ void w_prep_kernel(const float* __restrict__ w1, const float* __restrict__ w2) {
    int i = blockIdx.x * blockDim.x + threadIdx.x;
    if (i < 48 * 40) {
        int kk = i / 40, slot = i - kk * 40;
        int ky = kk >> 4, sl = kk & 15;
        float v = 0.f;
        if (slot < 32) {
            int ic = -1, kx = 0;
            if (sl < 3)                  { ic = sl;     kx = 0; }
            else if (sl >= 4 && sl < 7)  { ic = sl - 4; kx = 1; }
            else if (sl >= 8 && sl < 11) { ic = sl - 8; kx = 2; }
            if (ic >= 0) v = w1[slot * 27 + ic * 9 + ky * 3 + kx];
        }
        g_B1[i] = __float2bfloat16(v);
    }
    int i2 = i - 48 * 40;
    if (i2 >= 0 && i2 < 288 * 72) {
        int kk = i2 / 72, slot = i2 - kk * 72;
        int tap = kk >> 5, ic = kk & 31;
        float v = (slot < 64) ? w2[(slot * 32 + ic) * 9 + tap] : 0.f;
        g_B2[i2] = __float2bfloat16(v);
    }
}

template<int NT>
__device__ __forceinline__ void stage_x2(char* smc, int t, const float* __restrict__ x, int s) {
    const float* xb = x + (size_t)s * 12288;
    #pragma unroll
    for (int it = 0; it < 4096 / NT; it++) {
        int i = it * NT + t;
        float v0 = xb[i];
        float v1 = xb[4096 + i];
        float v2 = xb[8192 + i];
        uint2 q;
        q.x = pack_bf16x2(v0, v1);
        q.y = pack_bf16x2(v2, 0.f);
        int Y = (i >> 6) + 1, X = (i & 63) + 1;
        uint32_t off = X2_OFF + (uint32_t)(Y & 1) * X2_PY
                     + (uint32_t)((Y >> 1) * 33 + (X >> 1)) * 16u
                     + (uint32_t)(X & 1) * 8u;
        *(uint2*)(smc + off) = q;
    }
}

// ===========================================================================
// K1: persistent convs + pool (identical to R16 best)
// ===========================================================================
__global__ __launch_bounds__(NTHREADS, 1)
void gcp_conv_kernel(const float* __restrict__ x,
                     const float* __restrict__ b1, const float* __restrict__ b2)
{
    extern __shared__ char smc[];
    const uint32_t smaddr = smem_u32(smc);
    const int tid  = threadIdx.x;
    const int wrp  = tid >> 5;
    const int lane = tid & 31;
    float* vec = (float*)(smc + VEC_OFF);

    {
        uint4 z = make_uint4(0, 0, 0, 0);
        for (int i = tid; i < 2178; i += NTHREADS)
            ((uint4*)(smc + X2_OFF))[i] = z;
        for (int i = tid; i < 544; i += NTHREADS) {
            int c = i / 34, r = i - c * 34;
            int pyx = c >> 2, g = c & 3;
            int py = pyx >> 1, px = pyx & 1;
            int iy_h = (py == 0) ? 0 : 16;
            int ix_h = (px == 0) ? 0 : 16;
            int iy, ix;
            if (r < 17) { iy = iy_h; ix = r; }
            else        { iy = r - 17; ix = ix_h; }
            *(uint4*)(smc + P_OFF + (uint32_t)(pyx * 4 + g) * P_REG
                      + (uint32_t)(iy * 17 + ix) * 16u) = z;
        }
        const uint4* gb1 = (const uint4*)g_B1;
        for (int i = tid; i < 240; i += NTHREADS)
            ((uint4*)(smc + B1_OFF))[i] = gb1[i];
        const uint4* gb2 = (const uint4*)g_B2;
        for (int i = tid; i < 2592; i += NTHREADS)
            ((uint4*)(smc + B2_OFF))[i] = gb2[i];
        if (tid < 32) vec[V_B1S + tid] = b1[tid];
        else if (tid < 96) vec[V_B2S + tid - 32] = b2[tid - 32];
    }
    __syncthreads();
    if ((int)blockIdx.x < B_SAMPLES) stage_x2<NTHREADS>(smc, tid, x, blockIdx.x);
    __syncthreads();

    const int r8    = lane & 7;
    const int msel  = (lane >> 3) & 1;
    const int khsel = lane >> 4;
    const int stride = gridDim.x;
    const int ox2   = msel * 8 + r8;

    for (int s = blockIdx.x; s < B_SAMPLES; s += stride) {
        float acc1[2][4][4];
        #pragma unroll
        for (int mt = 0; mt < 2; mt++)
            #pragma unroll
            for (int nt = 0; nt < 4; nt++)
                #pragma unroll
                for (int rg = 0; rg < 4; rg++) acc1[mt][nt][rg] = 0.f;
        {
            #pragma unroll
            for (int ky = 0; ky < 3; ky++) {
                uint32_t bf[2][4];
                uint32_t bb = smaddr + B1_OFF + (uint32_t)(ky * 16 + (lane & 15)) * 80u
                              + (uint32_t)(lane >> 4) * 16u;
                ldsm_x4_t(bf[0], bb);
                ldsm_x4_t(bf[1], bb + 32u);

                const int pyA = ky & 1;
                uint32_t af[2][4];
                #pragma unroll
                for (int mt = 0; mt < 2; mt++) {
                    int pos = (wrp * 2 + mt) * 16 + msel * 8 + r8;
                    int oy1 = pos >> 5, ox1 = pos & 31;
                    int iyA = oy1 + (ky >> 1);
                    uint32_t addr = X2_OFF + (uint32_t)pyA * X2_PY
                                  + (uint32_t)(iyA * 33 + ox1 + khsel) * 16u;
                    ldsm_x4(af[mt], smaddr + addr);
                }
                #pragma unroll
                for (int mt = 0; mt < 2; mt++)
                    #pragma unroll
                    for (int nt = 0; nt < 4; nt++)
                        mma16816(acc1[mt][nt], af[mt], &bf[nt >> 1][(nt & 1) * 2]);
            }
        }
        {
            #pragma unroll
            for (int nt = 0; nt < 4; nt++) {
                int n = nt * 8 + (lane & 3) * 2;
                float bb0 = vec[V_B1S + n], bb1 = vec[V_B1S + n + 1];
                uint32_t greg = (uint32_t)(n >> 3) * P_REG;
                uint32_t sub  = (uint32_t)(n & 7) * 2u;
                #pragma unroll
                for (int mt = 0; mt < 2; mt++) {
                    #pragma unroll
                    for (int hh = 0; hh < 2; hh++) {
                        int pos = (wrp * 2 + mt) * 16 + (lane >> 2) + hh * 8;
                        int Y = (pos >> 5) + 1, X = (pos & 31) + 1;
                        float v0 = fmaxf(acc1[mt][nt][hh * 2 + 0] + bb0, 0.f);
                        float v1 = fmaxf(acc1[mt][nt][hh * 2 + 1] + bb1, 0.f);
                        uint32_t off = P_OFF + (uint32_t)((Y & 1) * 2 + (X & 1)) * (4u * P_REG)
                            + greg + (uint32_t)((Y >> 1) * 17 + (X >> 1)) * 16u + sub;
                        *(uint32_t*)(smc + off) = pack_bf16x2(v0, v1);
                    }
                }
            }
        }
        __syncthreads();   // A

        int sn = s + stride;
        if (wrp >= 16) {
            if (sn < B_SAMPLES) stage_x2<512>(smc, tid - 512, x, sn);
        } else {
            const int mt0 = (wrp & 7) * 2;
            const int nh  = wrp >> 3;
            float acc2[2][4][4];
            #pragma unroll
            for (int jl = 0; jl < 4; jl++) {
                int oc = nh * 32 + jl * 8 + (lane & 3) * 2;
                float b0  = vec[V_B2S + oc];
                float b1v = vec[V_B2S + oc + 1];
                #pragma unroll
                for (int mt = 0; mt < 2; mt++) {
                    acc2[mt][jl][0] = b0;  acc2[mt][jl][1] = b1v;
                    acc2[mt][jl][2] = b0;  acc2[mt][jl][3] = b1v;
                }
            }
            #pragma unroll
            for (int tap = 0; tap < 9; tap++) {
                const int ky = tap / 3, kx = tap - 3 * ky;
                const uint32_t pbase = P_OFF
                    + (uint32_t)((ky & 1) * 2 + (kx & 1)) * (4u * P_REG)
                    + (uint32_t)khsel * P_REG + (uint32_t)(ox2 + (kx >> 1)) * 16u;
                #pragma unroll
                for (int gh = 0; gh < 2; gh++) {
                    uint32_t af[2][4];
                    #pragma unroll
                    for (int mt = 0; mt < 2; mt++) {
                        uint32_t ra = pbase + (uint32_t)gh * (2u * P_REG)
                            + (uint32_t)((mt0 + mt + (ky >> 1)) * 17) * 16u;
                        ldsm_x4(af[mt], smaddr + ra);
                    }
                    uint32_t bf[2][4];
                    uint32_t bb = smaddr + B2_OFF
                        + (uint32_t)((tap * 32 + gh * 16) + (lane & 15)) * 144u
                        + (uint32_t)(lane >> 4) * 16u + (uint32_t)(2 * nh) * 32u;
                    ldsm_x4_t(bf[0], bb);
                    ldsm_x4_t(bf[1], bb + 32u);
                    #pragma unroll
                    for (int mt = 0; mt < 2; mt++)
                        #pragma unroll
                        for (int jl = 0; jl < 4; jl++)
                            mma16816(acc2[mt][jl], af[mt], &bf[jl >> 1][(jl & 1) * 2]);
                }
            }
            #pragma unroll
            for (int jl = 0; jl < 4; jl++) {
                float s0 = 0.f, s1 = 0.f;
                #pragma unroll
                for (int mt = 0; mt < 2; mt++) {
                    s0 += fmaxf(acc2[mt][jl][0], 0.f) + fmaxf(acc2[mt][jl][2], 0.f);
                    s1 += fmaxf(acc2[mt][jl][1], 0.f) + fmaxf(acc2[mt][jl][3], 0.f);
                }
                s0 += __shfl_xor_sync(0xffffffffu, s0, 4);
                s1 += __shfl_xor_sync(0xffffffffu, s1, 4);
                s0 += __shfl_xor_sync(0xffffffffu, s0, 8);
                s1 += __shfl_xor_sync(0xffffffffu, s1, 8);
                s0 += __shfl_xor_sync(0xffffffffu, s0, 16);
                s1 += __shfl_xor_sync(0xffffffffu, s1, 16);
                if (lane < 4) {
                    vec[V_PP + wrp * 32 + jl * 8 + lane * 2]     = s0;
                    vec[V_PP + wrp * 32 + jl * 8 + lane * 2 + 1] = s1;
                }
            }
        }
        __syncthreads();   // B

        if (tid < 64) {
            int nhh = tid >> 5, oc32 = tid & 31;
            float sacc = 0.f;
            #pragma unroll
            for (int mp = 0; mp < 8; mp++)
                sacc += vec[V_PP + (nhh * 8 + mp) * 32 + oc32];
            g_pool[s * 64 + nhh * 32 + oc32] = sacc * (1.f / 256.f);
        }
    }
}

// ===========================================================================
// K2: 32 samples per CTA; weights staged once into smem; register/shfl MLP.
// ===========================================================================
__global__ __launch_bounds__(1024, 1)
void gcp_mlp_kernel(const float* __restrict__ C,
                    const float* __restrict__ encw, const float* __restrict__ encb,
                    const float* __restrict__ f1w,  const float* __restrict__ f1b,
                    const float* __restrict__ f2w,  const float* __restrict__ f2b,
                    const float* __restrict__ f3w,  const float* __restrict__ f3b,
                    const float* __restrict__ f4w,  const float* __restrict__ f4b,
                    const float* __restrict__ f5w,  const float* __restrict__ f5b,
                    const float* __restrict__ ow,   const float* __restrict__ ob,
                    float* __restrict__ out)
{
    extern __shared__ float ws[];
    const int tid = threadIdx.x;

    // ---- stage all weights + biases into smem (coalesced) ----
    for (int i = tid; i < 8192;  i += 1024) ws[W_ENC + i] = encw[i];
    for (int i = tid; i < 6400;  i += 1024) ws[W_F1 + i]  = f1w[i];
    for (int i = tid; i < 6400;  i += 1024) ws[W_F2 + i]  = f2w[i];
    for (int i = tid; i < 16384; i += 1024) ws[W_F3 + i]  = f3w[i];
    for (int i = tid; i < 4096;  i += 1024) ws[W_F4 + i]  = f4w[i];
    for (int i = tid; i < 4096;  i += 1024) ws[W_F5 + i]  = f5w[i];
    for (int i = tid; i < 3200;  i += 1024) ws[W_OW + i]  = ow[i];
    if (tid < 128) ws[BB_ENC + tid] = encb[tid];
    else if (tid < 192) { int k = tid - 128; ws[BB_F1 + k] = (k < NVAR) ? f1b[k] : 0.f; }
    else if (tid < 320) ws[BB_F2 + tid - 192] = f2b[tid - 192];
    else if (tid < 384) ws[BB_F3 + tid - 320] = f3b[tid - 320];
    else if (tid < 448) ws[BB_F4 + tid - 384] = f4b[tid - 384];
    else if (tid < 512) ws[BB_F5 + tid - 448] = f5b[tid - 448];
    else if (tid < 576) { int k = tid - 512; ws[BB_OB + k] = (k < NVAR) ? ob[k] : 0.f; }
    __syncthreads();

    const int s    = blockIdx.x * 32 + (tid >> 5);
    const int lane = tid & 31;
    const unsigned FULL = 0xffffffffu;

    const float p0 = g_pool[s * 64 + lane];
    const float p1 = g_pool[s * 64 + 32 + lane];

    float x1r[4];
    #pragma unroll
    for (int j = 0; j < 4; j++) x1r[j] = ws[BB_ENC + lane + 32 * j];
    #pragma unroll 4
    for (int k = 0; k < 64; k++) {
        float v = (k < 32) ? __shfl_sync(FULL, p0, k) : __shfl_sync(FULL, p1, k - 32);
        #pragma unroll
        for (int j = 0; j < 4; j++)
            x1r[j] = fmaf(v, ws[W_ENC + k * 128 + lane + 32 * j], x1r[j]);
    }
    #pragma unroll
    for (int j = 0; j < 4; j++) x1r[j] = fmaxf(x1r[j], 0.f);

    float a0 = ws[BB_F1 + lane];
    float a1 = (lane < 18) ? ws[BB_F1 + lane + 32] : 0.f;
    const int nc = (lane < 18) ? lane + 32 : 49;
    #pragma unroll 4
    for (int k = 0; k < 128; k++) {
        float v = __shfl_sync(FULL, x1r[k >> 5], k & 31);
        a0 = fmaf(v, ws[W_F1 + k * NVAR + lane], a0);
        a1 = fmaf(v, ws[W_F1 + k * NVAR + nc], a1);
    }
    float x2a = fmaxf(a0, 0.f);
    float x2b = fmaxf(a1, 0.f);

    float ea = 0.f, eb = 0.f;
    {
        const float* cs = C + (size_t)s * 2500;
        for (int n = 0; n < NVAR; n++) {
            float t = __ldg(&cs[n * NVAR + lane]) * x2a;
            if (lane < 18) t = fmaf(__ldg(&cs[n * NVAR + 32 + lane]), x2b, t);
            #pragma unroll
            for (int off = 16; off > 0; off >>= 1)
                t += __shfl_xor_sync(FULL, t, off);
            if (n < 32) { if (lane == n) ea = t; }
            else        { if (lane == n - 32) eb = t; }
        }
    }

    float x3r[4];
    #pragma unroll
    for (int j = 0; j < 4; j++) x3r[j] = ws[BB_F2 + lane + 32 * j];
    #pragma unroll 2
    for (int k = 0; k < NVAR; k++) {
        float v = (k < 32) ? __shfl_sync(FULL, ea, k) : __shfl_sync(FULL, eb, k - 32);
        #pragma unroll
        for (int j = 0; j < 4; j++)
            x3r[j] = fmaf(v, ws[W_F2 + k * 128 + lane + 32 * j], x3r[j]);
    }
    #pragma unroll
    for (int j = 0; j < 4; j++) x3r[j] = fmaxf(x3r[j], 0.f);

    float b0 = ws[BB_F3 + lane], b1v = ws[BB_F3 + lane + 32];
    #pragma unroll 4
    for (int k = 0; k < 256; k++) {
        float v = (k < 128) ? __shfl_sync(FULL, x1r[k >> 5], k & 31)
                            : __shfl_sync(FULL, x3r[(k - 128) >> 5], (k - 128) & 31);
        b0  = fmaf(v, ws[W_F3 + k * 64 + lane], b0);
        b1v = fmaf(v, ws[W_F3 + k * 64 + lane + 32], b1v);
    }
    float x5a = fmaxf(b0, 0.f), x5b = fmaxf(b1v, 0.f);

    float c0 = ws[BB_F4 + lane], c1 = ws[BB_F4 + lane + 32];
    #pragma unroll 4
    for (int k = 0; k < 64; k++) {
        float v = (k < 32) ? __shfl_sync(FULL, x5a, k) : __shfl_sync(FULL, x5b, k - 32);
        c0 = fmaf(v, ws[W_F4 + k * 64 + lane], c0);
        c1 = fmaf(v, ws[W_F4 + k * 64 + lane + 32], c1);
    }
    float x6a = fmaxf(c0, 0.f), x6b = fmaxf(c1, 0.f);

    float d0 = ws[BB_F5 + lane], d1 = ws[BB_F5 + lane + 32];
    #pragma unroll 4
    for (int k = 0; k < 64; k++) {
        float v = (k < 32) ? __shfl_sync(FULL, x6a, k) : __shfl_sync(FULL, x6b, k - 32);
        d0 = fmaf(v, ws[W_F5 + k * 64 + lane], d0);
        d1 = fmaf(v, ws[W_F5 + k * 64 + lane + 32], d1);
    }
    float x7a = fmaxf(d0, 0.f), x7b = fmaxf(d1, 0.f);

    float l0 = ws[BB_OB + lane];
    float l1 = (lane < 18) ? ws[BB_OB + lane + 32] : 0.f;
    #pragma unroll 4
    for (int k = 0; k < 64; k++) {
        float v = (k < 32) ? __shfl_sync(FULL, x7a, k) : __shfl_sync(FULL, x7b, k - 32);
        l0 = fmaf(v, ws[W_OW + k * NVAR + lane], l0);
        l1 = fmaf(v, ws[W_OW + k * NVAR + nc], l1);
    }
    l0 = fmaxf(l0, 0.f);
    l1 = (lane < 18) ? fmaxf(l1, 0.f) : -1e30f;

    float m = fmaxf(l0, l1);
    #pragma unroll
    for (int off = 16; off > 0; off >>= 1)
        m = fmaxf(m, __shfl_xor_sync(FULL, m, off));
    float e0 = expf(l0 - m);
    float e1 = (lane < 18) ? expf(l1 - m) : 0.f;
    float ssum = e0 + e1;
    #pragma unroll
    for (int off = 16; off > 0; off >>= 1)
        ssum += __shfl_xor_sync(FULL, ssum, off);
    float inv = 1.f / ssum;
    out[s * NVAR + lane] = e0 * inv;
    if (lane < 18) out[s * NVAR + 32 + lane] = e1 * inv;
}

extern "C" void kernel_launch(void* const* d_in, const int* in_sizes, int n_in,
                              void* d_out, int out_size)
{
    (void)in_sizes; (void)n_in; (void)out_size;
    const float* x    = (const float*)d_in[0];
    const float* C    = (const float*)d_in[1];
    const float* w1   = (const float*)d_in[2];
    const float* b1   = (const float*)d_in[3];
    const float* w2   = (const float*)d_in[4];
    const float* b2   = (const float*)d_in[5];
    const float* encw = (const float*)d_in[6];
    const float* encb = (const float*)d_in[7];
    const float* f1w  = (const float*)d_in[8];
    const float* f1b  = (const float*)d_in[9];
    const float* f2w  = (const float*)d_in[10];
    const float* f2b  = (const float*)d_in[11];
    const float* f3w  = (const float*)d_in[12];
    const float* f3b  = (const float*)d_in[13];
    const float* f4w  = (const float*)d_in[14];
    const float* f4b  = (const float*)d_in[15];
    const float* f5w  = (const float*)d_in[16];
    const float* f5b  = (const float*)d_in[17];
    const float* ow   = (const float*)d_in[18];
    const float* ob   = (const float*)d_in[19];
    float* out = (float*)d_out;

    int nsm = 148;
    cudaDeviceGetAttribute(&nsm, cudaDevAttrMultiProcessorCount, 0);

    w_prep_kernel<<<89, 256>>>(w1, w2);

    cudaFuncSetAttribute(gcp_conv_kernel,
                         cudaFuncAttributeMaxDynamicSharedMemorySize, SMEM_BYTES);
    gcp_conv_kernel<<<nsm, NTHREADS, SMEM_BYTES>>>(x, b1, b2);

    cudaFuncSetAttribute(gcp_mlp_kernel,
                         cudaFuncAttributeMaxDynamicSharedMemorySize, K2_SMEM_BYTES);
    gcp_mlp_kernel<<<B_SAMPLES / 32, 1024, K2_SMEM_BYTES>>>(
        C, encw, encb, f1w, f1b, f2w, f2b,
        f3w, f3b, f4w, f4b, f5w, f5b, ow, ob, out);
}